// round 14
// baseline (speedup 1.0000x reference)
#include <cuda_runtime.h>
#include <cuda_bf16.h>
#include <cfloat>

// Problem constants
#define NN 50000
#define EE 800000
#define FIN 256
#define NH 4
#define DD 64
#define OO 256   // NH*DD
#define NT 8     // etypes

// ---------------- device scratch (allocation-free rule: __device__ globals) ----
__device__ float g_ft[(size_t)NN * OO];      // 51.2 MB
__device__ float g_el[NN * NH];
__device__ float g_er[NN * NH];
__device__ int   g_counts[NN + 1];
__device__ int   g_offsets[NN + 1];
__device__ int   g_cursor[NN];
__device__ int   g_srcArr[EE];
__device__ float g_eArr[(size_t)EE * NH];    // logits -> exp -> a (in place)

__device__ __forceinline__ float lrelu(float x, float s) {
    return x >= 0.f ? x : s * x;
}

// ---------------- 0) zero the histogram ----------------
__global__ void k_zero() {
    int i = blockIdx.x * blockDim.x + threadIdx.x;
    if (i <= NN) g_counts[i] = 0;
}

// ---------------- 1) SGEMM: ft[M,256] = feat[M,256] @ fc_w[256,256]^T ----------
// 128x128 tile, BK=16, 256 threads, 8x8 per thread.
__global__ __launch_bounds__(256) void k_gemm(const float* __restrict__ A,
                                              const float* __restrict__ W) {
    const int BM = 128, BN = 128, BK = 16;
    __shared__ float As[BK][BM];
    __shared__ float Bs[BK][BN];

    int tid = threadIdx.x;
    int bm = blockIdx.x * BM;
    int bn = blockIdx.y * BN;
    int tx = tid & 15;        // 0..15 -> col group
    int ty = tid >> 4;        // 0..15 -> row group

    int lr = tid >> 2;        // 0..63 row within tile for loads
    int lc = (tid & 3) * 4;   // k offset {0,4,8,12}

    float acc[8][8];
#pragma unroll
    for (int i = 0; i < 8; i++)
#pragma unroll
        for (int j = 0; j < 8; j++) acc[i][j] = 0.f;

    for (int k0 = 0; k0 < FIN; k0 += BK) {
#pragma unroll
        for (int r = 0; r < 2; r++) {
            int row = bm + lr + r * 64;
            float4 v = make_float4(0.f, 0.f, 0.f, 0.f);
            if (row < NN) v = *(const float4*)&A[(size_t)row * FIN + k0 + lc];
            As[lc + 0][lr + r * 64] = v.x;
            As[lc + 1][lr + r * 64] = v.y;
            As[lc + 2][lr + r * 64] = v.z;
            As[lc + 3][lr + r * 64] = v.w;
        }
#pragma unroll
        for (int r = 0; r < 2; r++) {
            int o = bn + lr + r * 64;   // always < 256
            float4 v = *(const float4*)&W[(size_t)o * FIN + k0 + lc];
            Bs[lc + 0][lr + r * 64] = v.x;
            Bs[lc + 1][lr + r * 64] = v.y;
            Bs[lc + 2][lr + r * 64] = v.z;
            Bs[lc + 3][lr + r * 64] = v.w;
        }
        __syncthreads();

#pragma unroll
        for (int kk = 0; kk < BK; kk++) {
            float a[8], b[8];
            float4 a0 = *(const float4*)&As[kk][ty * 8];
            float4 a1 = *(const float4*)&As[kk][ty * 8 + 4];
            float4 b0 = *(const float4*)&Bs[kk][tx * 8];
            float4 b1 = *(const float4*)&Bs[kk][tx * 8 + 4];
            a[0]=a0.x; a[1]=a0.y; a[2]=a0.z; a[3]=a0.w;
            a[4]=a1.x; a[5]=a1.y; a[6]=a1.z; a[7]=a1.w;
            b[0]=b0.x; b[1]=b0.y; b[2]=b0.z; b[3]=b0.w;
            b[4]=b1.x; b[5]=b1.y; b[6]=b1.z; b[7]=b1.w;
#pragma unroll
            for (int i = 0; i < 8; i++)
#pragma unroll
                for (int j = 0; j < 8; j++) acc[i][j] += a[i] * b[j];
        }
        __syncthreads();
    }

#pragma unroll
    for (int i = 0; i < 8; i++) {
        int row = bm + ty * 8 + i;
        if (row < NN) {
            float4 v0 = make_float4(acc[i][0], acc[i][1], acc[i][2], acc[i][3]);
            float4 v1 = make_float4(acc[i][4], acc[i][5], acc[i][6], acc[i][7]);
            *(float4*)&g_ft[(size_t)row * OO + bn + tx * 8]     = v0;
            *(float4*)&g_ft[(size_t)row * OO + bn + tx * 8 + 4] = v1;
        }
    }
}

// ---------------- 2) el/er: one warp per (node, head) ----------------
__global__ void k_elr(const float* __restrict__ attn_l,
                      const float* __restrict__ attn_r) {
    int w = (blockIdx.x * blockDim.x + threadIdx.x) >> 5;
    if (w >= NN * NH) return;
    int lane = threadIdx.x & 31;
    int n = w >> 2, h = w & 3;

    float2 f  = *(const float2*)&g_ft[(size_t)n * OO + h * DD + lane * 2];
    float2 al = *(const float2*)&attn_l[h * DD + lane * 2];
    float2 ar = *(const float2*)&attn_r[h * DD + lane * 2];
    float pl = f.x * al.x + f.y * al.y;
    float pr = f.x * ar.x + f.y * ar.y;
#pragma unroll
    for (int off = 16; off > 0; off >>= 1) {
        pl += __shfl_xor_sync(0xffffffffu, pl, off);
        pr += __shfl_xor_sync(0xffffffffu, pr, off);
    }
    if (lane == 0) {
        g_el[n * NH + h] = pl;
        g_er[n * NH + h] = pr;
    }
}

// ---------------- 3) histogram of dst ----------------
__global__ void k_count(const int* __restrict__ dst) {
    int e = blockIdx.x * blockDim.x + threadIdx.x;
    if (e < EE) atomicAdd(&g_counts[dst[e]], 1);
}

// ---------------- 4) single-block exclusive scan ----------------
__global__ void k_scan() {
    __shared__ int sh[1024];
    __shared__ int carry;
    int tid = threadIdx.x;
    if (tid == 0) carry = 0;
    __syncthreads();
    for (int base = 0; base < NN; base += 1024) {
        int i = base + tid;
        int v = (i < NN) ? g_counts[i] : 0;
        sh[tid] = v;
        __syncthreads();
#pragma unroll
        for (int off = 1; off < 1024; off <<= 1) {
            int t = (tid >= off) ? sh[tid - off] : 0;
            __syncthreads();
            sh[tid] += t;
            __syncthreads();
        }
        int incl = sh[tid];
        int excl = incl - v;
        if (i < NN) {
            g_offsets[i] = carry + excl;
            g_cursor[i]  = carry + excl;
        }
        __syncthreads();
        if (tid == 1023) carry += incl;
        __syncthreads();
    }
    if (tid == 0) g_offsets[NN] = carry;
}

// ---------------- 5) per-edge logits + CSR scatter ----------------
__global__ void k_edge(const int* __restrict__ src, const int* __restrict__ dst,
                       const int* __restrict__ etype,
                       const float* __restrict__ edge_weight) {
    int e = blockIdx.x * blockDim.x + threadIdx.x;
    if (e >= EE) return;
    int s = src[e], d = dst[e], t = etype[e] - 1;
    int pos = atomicAdd(&g_cursor[d], 1);
    g_srcArr[pos] = s;
    float4 elv = *(const float4*)&g_el[s * NH];
    float4 erv = *(const float4*)&g_er[d * NH];
    float el4[4] = {elv.x, elv.y, elv.z, elv.w};
    float er4[4] = {erv.x, erv.y, erv.z, erv.w};
    float out[4];
#pragma unroll
    for (int h = 0; h < NH; h++) {
        float ew = lrelu(edge_weight[t * NH + h] * 100.0f, 0.01f);
        out[h] = lrelu((el4[h] + er4[h]) * ew, 0.2f);
    }
    *(float4*)&g_eArr[(size_t)pos * NH] = make_float4(out[0], out[1], out[2], out[3]);
}

// ---------------- 6) per-node edge softmax (one warp per node) -------------
// Values for node n live at g_eArr[beg*4 .. end*4), layout [deg][4].
// Stride-32 lane access keeps h = lane&3 constant -> reduce over xor 4,8,16.
__global__ void k_soft() {
    int w = (blockIdx.x * blockDim.x + threadIdx.x) >> 5;
    if (w >= NN) return;
    int lane = threadIdx.x & 31;
    int beg = g_offsets[w], end = g_offsets[w + 1];
    int m = (end - beg) * NH;
    float* ep = g_eArr + (size_t)beg * NH;

    float mx = -FLT_MAX;
    for (int j = lane; j < m; j += 32) mx = fmaxf(mx, ep[j]);
    mx = fmaxf(mx, __shfl_xor_sync(0xffffffffu, mx, 4));
    mx = fmaxf(mx, __shfl_xor_sync(0xffffffffu, mx, 8));
    mx = fmaxf(mx, __shfl_xor_sync(0xffffffffu, mx, 16));

    float sum = 0.f;
    for (int j = lane; j < m; j += 32) {
        float ex = __expf(ep[j] - mx);
        ep[j] = ex;
        sum += ex;
    }
    sum += __shfl_xor_sync(0xffffffffu, sum, 4);
    sum += __shfl_xor_sync(0xffffffffu, sum, 8);
    sum += __shfl_xor_sync(0xffffffffu, sum, 16);

    float inv = 1.f / sum;
    for (int j = lane; j < m; j += 32) ep[j] *= inv;
}

// ---------------- 7) aggregation: one 256-thread block per node -------------
__global__ __launch_bounds__(256) void k_agg(float* __restrict__ rst) {
    __shared__ int   ssrc[64];
    __shared__ float sa[64 * NH];
    int n = blockIdx.x;
    int d = threadIdx.x;          // 0..255 -> output dim
    int h = d >> 6;               // head
    int beg = g_offsets[n], end = g_offsets[n + 1];

    float acc = 0.f;
    for (int base = beg; base < end; base += 64) {
        int cnt = min(64, end - base);
        if (d < cnt) ssrc[d] = g_srcArr[base + d];
        for (int j = d; j < cnt * NH; j += 256) sa[j] = g_eArr[(size_t)base * NH + j];
        __syncthreads();

        int j = 0;
        for (; j + 4 <= cnt; j += 4) {
            float f0 = g_ft[(size_t)ssrc[j + 0] * OO + d];
            float f1 = g_ft[(size_t)ssrc[j + 1] * OO + d];
            float f2 = g_ft[(size_t)ssrc[j + 2] * OO + d];
            float f3 = g_ft[(size_t)ssrc[j + 3] * OO + d];
            acc += f0 * sa[(j + 0) * NH + h];
            acc += f1 * sa[(j + 1) * NH + h];
            acc += f2 * sa[(j + 2) * NH + h];
            acc += f3 * sa[(j + 3) * NH + h];
        }
        for (; j < cnt; j++)
            acc += g_ft[(size_t)ssrc[j] * OO + d] * sa[j * NH + h];
        __syncthreads();
    }
    rst[(size_t)n * OO + d] = acc;
}

// ---------------- launch ----------------
extern "C" void kernel_launch(void* const* d_in, const int* in_sizes, int n_in,
                              void* d_out, int out_size) {
    const float* feat        = (const float*)d_in[0];
    const int*   src         = (const int*)d_in[1];
    const int*   dst         = (const int*)d_in[2];
    const int*   edge_feats  = (const int*)d_in[3];
    const float* fc_w        = (const float*)d_in[4];
    const float* attn_l      = (const float*)d_in[5];
    const float* attn_r      = (const float*)d_in[6];
    const float* edge_weight = (const float*)d_in[7];
    float* rst = (float*)d_out;

    k_zero<<<(NN + 1 + 255) / 256, 256>>>();
    {
        dim3 grid((NN + 127) / 128, OO / 128);
        k_gemm<<<grid, 256>>>(feat, fc_w);
    }
    k_elr<<<(NN * NH + 7) / 8, 256>>>(attn_l, attn_r);
    k_count<<<(EE + 255) / 256, 256>>>(dst);
    k_scan<<<1, 1024>>>();
    k_edge<<<(EE + 255) / 256, 256>>>(src, dst, edge_feats, edge_weight);
    k_soft<<<(NN + 7) / 8, 256>>>();
    k_agg<<<NN, 256>>>(rst);
}

// round 15
// speedup vs baseline: 1.0736x; 1.0736x over previous
#include <cuda_runtime.h>
#include <cuda_bf16.h>
#include <cfloat>

// Problem constants
#define NN 50000
#define EE 800000
#define FIN 256
#define NH 4
#define DD 64
#define OO 256   // NH*DD
#define NT 8     // etypes

// ---------------- device scratch (allocation-free rule: __device__ globals) ----
__device__ float g_ft[(size_t)NN * OO];      // 51.2 MB
__device__ float g_el[NN * NH];
__device__ float g_er[NN * NH];
__device__ int   g_counts[NN + 1];
__device__ int   g_offsets[NN + 1];
__device__ int   g_cursor[NN];
__device__ int   g_srcArr[EE];
__device__ float g_eArr[(size_t)EE * NH];    // logits -> exp -> a (in place)

__device__ __forceinline__ float lrelu(float x, float s) {
    return x >= 0.f ? x : s * x;
}

// Packed fp32 FMA (Blackwell FFMA2) — only reachable via PTX fma.rn.f32x2.
__device__ __forceinline__ void ffma2(unsigned long long& d,
                                      unsigned long long a,
                                      unsigned long long b) {
    asm("fma.rn.f32x2 %0, %1, %2, %0;" : "+l"(d) : "l"(a), "l"(b));
}
__device__ __forceinline__ unsigned long long dup2(float x) {
    unsigned long long r;
    unsigned u = __float_as_uint(x);
    asm("mov.b64 %0, {%1, %1};" : "=l"(r) : "r"(u));
    return r;
}

// ---------------- 0) zero the histogram ----------------
__global__ void k_zero() {
    int i = blockIdx.x * blockDim.x + threadIdx.x;
    if (i <= NN) g_counts[i] = 0;
}

// ---------------- 1) SGEMM: ft[M,256] = feat[M,256] @ fc_w[256,256]^T ----------
// 128x128 tile, BK=16, 256 threads, 8x8 per thread via packed f32x2 FMA.
__global__ __launch_bounds__(256) void k_gemm(const float* __restrict__ A,
                                              const float* __restrict__ W) {
    const int BM = 128, BN = 128, BK = 16;
    __shared__ float As[BK][BM];
    __shared__ float Bs[BK][BN];

    int tid = threadIdx.x;
    int bm = blockIdx.x * BM;
    int bn = blockIdx.y * BN;
    int tx = tid & 15;        // 0..15 -> col group
    int ty = tid >> 4;        // 0..15 -> row group

    int lr = tid >> 2;        // 0..63 row within tile for loads
    int lc = (tid & 3) * 4;   // k offset {0,4,8,12}

    // acc2[i][j] holds output columns (2j, 2j+1) for row i — packed fp32 pairs.
    unsigned long long acc2[8][4];
#pragma unroll
    for (int i = 0; i < 8; i++)
#pragma unroll
        for (int j = 0; j < 4; j++) acc2[i][j] = 0ull;

    for (int k0 = 0; k0 < FIN; k0 += BK) {
#pragma unroll
        for (int r = 0; r < 2; r++) {
            int row = bm + lr + r * 64;
            float4 v = make_float4(0.f, 0.f, 0.f, 0.f);
            if (row < NN) v = *(const float4*)&A[(size_t)row * FIN + k0 + lc];
            As[lc + 0][lr + r * 64] = v.x;
            As[lc + 1][lr + r * 64] = v.y;
            As[lc + 2][lr + r * 64] = v.z;
            As[lc + 3][lr + r * 64] = v.w;
        }
#pragma unroll
        for (int r = 0; r < 2; r++) {
            int o = bn + lr + r * 64;   // always < 256
            float4 v = *(const float4*)&W[(size_t)o * FIN + k0 + lc];
            Bs[lc + 0][lr + r * 64] = v.x;
            Bs[lc + 1][lr + r * 64] = v.y;
            Bs[lc + 2][lr + r * 64] = v.z;
            Bs[lc + 3][lr + r * 64] = v.w;
        }
        __syncthreads();

#pragma unroll
        for (int kk = 0; kk < BK; kk++) {
            float a[8];
            float4 a0 = *(const float4*)&As[kk][ty * 8];
            float4 a1 = *(const float4*)&As[kk][ty * 8 + 4];
            a[0]=a0.x; a[1]=a0.y; a[2]=a0.z; a[3]=a0.w;
            a[4]=a1.x; a[5]=a1.y; a[6]=a1.z; a[7]=a1.w;
            // b pairs: 4 x 64-bit loads from shared (consecutive fp32 pairs)
            ulonglong2 bb0 = *(const ulonglong2*)&Bs[kk][tx * 8];
            ulonglong2 bb1 = *(const ulonglong2*)&Bs[kk][tx * 8 + 4];
            unsigned long long b2[4] = {bb0.x, bb0.y, bb1.x, bb1.y};
#pragma unroll
            for (int i = 0; i < 8; i++) {
                unsigned long long a2 = dup2(a[i]);
#pragma unroll
                for (int j = 0; j < 4; j++) ffma2(acc2[i][j], a2, b2[j]);
            }
        }
        __syncthreads();
    }

#pragma unroll
    for (int i = 0; i < 8; i++) {
        int row = bm + ty * 8 + i;
        if (row < NN) {
            ulonglong2 v0 = make_ulonglong2(acc2[i][0], acc2[i][1]);
            ulonglong2 v1 = make_ulonglong2(acc2[i][2], acc2[i][3]);
            *(ulonglong2*)&g_ft[(size_t)row * OO + bn + tx * 8]     = v0;
            *(ulonglong2*)&g_ft[(size_t)row * OO + bn + tx * 8 + 4] = v1;
        }
    }
}

// ---------------- 2) el/er: one warp per (node, head) ----------------
__global__ void k_elr(const float* __restrict__ attn_l,
                      const float* __restrict__ attn_r) {
    int w = (blockIdx.x * blockDim.x + threadIdx.x) >> 5;
    if (w >= NN * NH) return;
    int lane = threadIdx.x & 31;
    int n = w >> 2, h = w & 3;

    float2 f  = *(const float2*)&g_ft[(size_t)n * OO + h * DD + lane * 2];
    float2 al = *(const float2*)&attn_l[h * DD + lane * 2];
    float2 ar = *(const float2*)&attn_r[h * DD + lane * 2];
    float pl = f.x * al.x + f.y * al.y;
    float pr = f.x * ar.x + f.y * ar.y;
#pragma unroll
    for (int off = 16; off > 0; off >>= 1) {
        pl += __shfl_xor_sync(0xffffffffu, pl, off);
        pr += __shfl_xor_sync(0xffffffffu, pr, off);
    }
    if (lane == 0) {
        g_el[n * NH + h] = pl;
        g_er[n * NH + h] = pr;
    }
}

// ---------------- 3) histogram of dst ----------------
__global__ void k_count(const int* __restrict__ dst) {
    int e = blockIdx.x * blockDim.x + threadIdx.x;
    if (e < EE) atomicAdd(&g_counts[dst[e]], 1);
}

// ---------------- 4) single-block exclusive scan (warp-shuffle based) --------
__global__ void k_scan() {
    __shared__ int wsum[32];
    __shared__ int carry_s;
    int tid = threadIdx.x;
    int lane = tid & 31, wid = tid >> 5;
    if (tid == 0) carry_s = 0;
    __syncthreads();
    for (int base = 0; base < NN; base += 1024) {
        int i = base + tid;
        int v = (i < NN) ? g_counts[i] : 0;
        int x = v;
#pragma unroll
        for (int off = 1; off < 32; off <<= 1) {
            int t = __shfl_up_sync(0xffffffffu, x, off);
            if (lane >= off) x += t;
        }
        if (lane == 31) wsum[wid] = x;
        __syncthreads();
        if (wid == 0) {
            int s = wsum[lane];
#pragma unroll
            for (int off = 1; off < 32; off <<= 1) {
                int t = __shfl_up_sync(0xffffffffu, s, off);
                if (lane >= off) s += t;
            }
            wsum[lane] = s;
        }
        __syncthreads();
        int warppref = (wid > 0) ? wsum[wid - 1] : 0;
        int excl = x + warppref - v;
        int c = carry_s;
        if (i < NN) {
            g_offsets[i] = c + excl;
            g_cursor[i]  = c + excl;
        }
        __syncthreads();
        if (tid == 1023) carry_s = c + wsum[31];
        __syncthreads();
    }
    if (tid == 0) g_offsets[NN] = carry_s;
}

// ---------------- 5) per-edge logits + CSR scatter ----------------
__global__ void k_edge(const int* __restrict__ src, const int* __restrict__ dst,
                       const int* __restrict__ etype,
                       const float* __restrict__ edge_weight) {
    int e = blockIdx.x * blockDim.x + threadIdx.x;
    if (e >= EE) return;
    int s = src[e], d = dst[e], t = etype[e] - 1;
    int pos = atomicAdd(&g_cursor[d], 1);
    g_srcArr[pos] = s;
    float4 elv = *(const float4*)&g_el[s * NH];
    float4 erv = *(const float4*)&g_er[d * NH];
    float el4[4] = {elv.x, elv.y, elv.z, elv.w};
    float er4[4] = {erv.x, erv.y, erv.z, erv.w};
    float out[4];
#pragma unroll
    for (int h = 0; h < NH; h++) {
        float ew = lrelu(edge_weight[t * NH + h] * 100.0f, 0.01f);
        out[h] = lrelu((el4[h] + er4[h]) * ew, 0.2f);
    }
    *(float4*)&g_eArr[(size_t)pos * NH] = make_float4(out[0], out[1], out[2], out[3]);
}

// ---------------- 6) per-node edge softmax (one warp per node) -------------
__global__ void k_soft() {
    int w = (blockIdx.x * blockDim.x + threadIdx.x) >> 5;
    if (w >= NN) return;
    int lane = threadIdx.x & 31;
    int beg = g_offsets[w], end = g_offsets[w + 1];
    int m = (end - beg) * NH;
    float* ep = g_eArr + (size_t)beg * NH;

    float mx = -FLT_MAX;
    for (int j = lane; j < m; j += 32) mx = fmaxf(mx, ep[j]);
    mx = fmaxf(mx, __shfl_xor_sync(0xffffffffu, mx, 4));
    mx = fmaxf(mx, __shfl_xor_sync(0xffffffffu, mx, 8));
    mx = fmaxf(mx, __shfl_xor_sync(0xffffffffu, mx, 16));

    float sum = 0.f;
    for (int j = lane; j < m; j += 32) {
        float ex = __expf(ep[j] - mx);
        ep[j] = ex;
        sum += ex;
    }
    sum += __shfl_xor_sync(0xffffffffu, sum, 4);
    sum += __shfl_xor_sync(0xffffffffu, sum, 8);
    sum += __shfl_xor_sync(0xffffffffu, sum, 16);

    float inv = 1.f / sum;
    for (int j = lane; j < m; j += 32) ep[j] *= inv;
}

// ---------------- 7) aggregation: one 256-thread block per node -------------
__global__ __launch_bounds__(256) void k_agg(float* __restrict__ rst) {
    __shared__ int   ssrc[64];
    __shared__ float sa[64 * NH];
    int n = blockIdx.x;
    int d = threadIdx.x;          // 0..255 -> output dim
    int h = d >> 6;               // head
    int beg = g_offsets[n], end = g_offsets[n + 1];

    float acc = 0.f;
    for (int base = beg; base < end; base += 64) {
        int cnt = min(64, end - base);
        if (d < cnt) ssrc[d] = g_srcArr[base + d];
        for (int j = d; j < cnt * NH; j += 256) sa[j] = g_eArr[(size_t)base * NH + j];
        __syncthreads();

        int j = 0;
        for (; j + 4 <= cnt; j += 4) {
            float f0 = g_ft[(size_t)ssrc[j + 0] * OO + d];
            float f1 = g_ft[(size_t)ssrc[j + 1] * OO + d];
            float f2 = g_ft[(size_t)ssrc[j + 2] * OO + d];
            float f3 = g_ft[(size_t)ssrc[j + 3] * OO + d];
            acc += f0 * sa[(j + 0) * NH + h];
            acc += f1 * sa[(j + 1) * NH + h];
            acc += f2 * sa[(j + 2) * NH + h];
            acc += f3 * sa[(j + 3) * NH + h];
        }
        for (; j < cnt; j++)
            acc += g_ft[(size_t)ssrc[j] * OO + d] * sa[j * NH + h];
        __syncthreads();
    }
    rst[(size_t)n * OO + d] = acc;
}

// ---------------- launch ----------------
extern "C" void kernel_launch(void* const* d_in, const int* in_sizes, int n_in,
                              void* d_out, int out_size) {
    const float* feat        = (const float*)d_in[0];
    const int*   src         = (const int*)d_in[1];
    const int*   dst         = (const int*)d_in[2];
    const int*   edge_feats  = (const int*)d_in[3];
    const float* fc_w        = (const float*)d_in[4];
    const float* attn_l      = (const float*)d_in[5];
    const float* attn_r      = (const float*)d_in[6];
    const float* edge_weight = (const float*)d_in[7];
    float* rst = (float*)d_out;

    k_zero<<<(NN + 1 + 255) / 256, 256>>>();
    {
        dim3 grid((NN + 127) / 128, OO / 128);
        k_gemm<<<grid, 256>>>(feat, fc_w);
    }
    k_elr<<<(NN * NH + 7) / 8, 256>>>(attn_l, attn_r);
    k_count<<<(EE + 255) / 256, 256>>>(dst);
    k_scan<<<1, 1024>>>();
    k_edge<<<(EE + 255) / 256, 256>>>(src, dst, edge_feats, edge_weight);
    k_soft<<<(NN + 7) / 8, 256>>>();
    k_agg<<<NN, 256>>>(rst);
}